// round 8
// baseline (speedup 1.0000x reference)
#include <cuda_runtime.h>

#define DEPTH 10
#define WIDTH 512
#define LVL_ELEMS (DEPTH * WIDTH)   // 5120 floats per (b,t)
#define TPB 128                     // 4 columns per thread

__device__ __forceinline__ float sigmoidf(float v) {
    // sigmoid(x) = 0.5 * tanh(x/2) + 0.5 — single MUFU (HW tanh) + MUL + FMA
    float t;
    asm("tanh.approx.f32 %0, %1;" : "=f"(t) : "f"(v * 0.5f));
    return fmaf(t, 0.5f, 0.5f);
}

template <int W>
__device__ __forceinline__ float allred(float v) {
    #pragma unroll
    for (int ofs = 1; ofs < W; ofs <<= 1)
        v += __shfl_xor_sync(0xffffffffu, v, ofs);
    return v;
}

struct BtSums {
    float  sum4[DEPTH];
    float4 sg8, sg9;
};

__device__ __forceinline__ void load_bt(const float* __restrict__ x, int bt,
                                        int tid, float4 v[DEPTH]) {
    const float4* __restrict__ x4 =
        reinterpret_cast<const float4*>(x) + (size_t)bt * (LVL_ELEMS / 4) + tid;
    // 10 independent streaming LDG.128 (evict-first: data is never reused)
    #pragma unroll
    for (int j = 0; j < DEPTH; ++j) v[j] = __ldcs(&x4[j * (WIDTH / 4)]);
}

__device__ __forceinline__ void sig_phase(const float4 v[DEPTH], BtSums& s) {
    #pragma unroll
    for (int j = 0; j < DEPTH; ++j) {
        float a = sigmoidf(v[j].x);
        float b = sigmoidf(v[j].y);
        float c = sigmoidf(v[j].z);
        float d = sigmoidf(v[j].w);
        s.sum4[j] = (a + b) + (c + d);
        if (j == 8) s.sg8 = make_float4(a, b, c, d);
        if (j == 9) s.sg9 = make_float4(a, b, c, d);
    }
}

// Shuffle/smem reduction + tree contraction + store. Uses smem bank `p` (0/1)
// so the two per-block bt phases never race on the same words.
__device__ __forceinline__ void reduce_phase(const BtSums& s, float* __restrict__ out,
                                             int bt, int tid, int warp, int lane,
                                             float (*ws0)[4], float (*ws1)[4],
                                             float (*wsf)[4], int p) {
    float d1[8];
    d1[7] = s.sum4[7] * 0.25f;                       // 1 thread
    d1[6] = allred<2>(s.sum4[6])  * (1.0f / 8.0f);   // 2 threads
    d1[5] = allred<4>(s.sum4[5])  * (1.0f / 16.0f);
    d1[4] = allred<8>(s.sum4[4])  * (1.0f / 32.0f);
    d1[3] = allred<16>(s.sum4[3]) * (1.0f / 64.0f);
    d1[2] = allred<32>(s.sum4[2]) * (1.0f / 128.0f); // full warp

    float w1 = allred<32>(s.sum4[1]);
    float w0 = allred<32>(s.sum4[0]);
    if (lane == 0) { ws1[p][warp] = w1; ws0[p][warp] = w0; }
    __syncthreads();
    d1[1] = (ws1[p][warp] + ws1[p][warp ^ 1]) * (1.0f / 256.0f);
    d1[0] = ((ws0[p][0] + ws0[p][1]) + (ws0[p][2] + ws0[p][3])) * (1.0f / 512.0f);

    // Path product for levels 0..6 — identical for all 4 leaves of this thread.
    float common = 1.0f;
    #pragma unroll
    for (int j = 0; j <= 6; ++j) {
        int bit = (tid >> (6 - j)) & 1;
        common *= bit ? d1[j] : (1.0f - d1[j]);
    }

    // Levels 7..9 in closed form over this thread's 4 leaves.
    float d8a  = (s.sg8.x + s.sg8.y) * 0.5f;
    float d8b  = (s.sg8.z + s.sg8.w) * 0.5f;
    float left  = (1.0f - d8a) * s.sg9.x + d8a * s.sg9.y;
    float right = (1.0f - d8b) * s.sg9.z + d8b * s.sg9.w;
    float tv = common * ((1.0f - d1[7]) * left + d1[7] * right);

    tv = allred<32>(tv);
    if (lane == 0) wsf[p][warp] = tv;
    __syncthreads();
    if (tid == 0) out[bt] = (wsf[p][0] + wsf[p][1]) + (wsf[p][2] + wsf[p][3]);
}

__global__ void __launch_bounds__(TPB, 5)
NCT_82162724372482_kernel(const float* __restrict__ x, float* __restrict__ out,
                          int n_bt) {
    __shared__ float ws0[2][4], ws1[2][4], wsf[2][4];

    const int tid  = threadIdx.x;
    const int warp = tid >> 5;
    const int lane = tid & 31;

    const int bt0 = blockIdx.x * 2;      // this block owns bt0, bt0+1 (adjacent)
    const int bt1 = bt0 + 1;

    float4 va[DEPTH], vb[DEPTH];
    BtSums sa, sb;

    // Pipeline: loads(A) -> sig(A) -> loads(B) -> reduce(A) -> sig(B) -> reduce(B)
    // B's 10 LDG.128 are in flight during A's entire shuffle/smem reduction chain.
    load_bt(x, bt0, tid, va);
    sig_phase(va, sa);

    const bool has_b = (bt1 < n_bt);
    if (has_b) load_bt(x, bt1, tid, vb);

    reduce_phase(sa, out, bt0, tid, warp, lane, ws0, ws1, wsf, 0);

    if (has_b) {
        sig_phase(vb, sb);
        reduce_phase(sb, out, bt1, tid, warp, lane, ws0, ws1, wsf, 1);
    }
}

extern "C" void kernel_launch(void* const* d_in, const int* in_sizes, int n_in,
                              void* d_out, int out_size) {
    const float* x = (const float*)d_in[0];
    float* out = (float*)d_out;
    const int n_bt = in_sizes[0] / LVL_ELEMS;   // BATCH * NUM_TREES = 16384
    const int blocks = (n_bt + 1) / 2;          // 2 bt per block
    NCT_82162724372482_kernel<<<blocks, TPB>>>(x, out, n_bt);
}